// round 4
// baseline (speedup 1.0000x reference)
#include <cuda_runtime.h>
#include <cuda_bf16.h>
#include <cstdint>

// Problem constants
#define BATCH 64
#define TSTEPS 2048
#define DIN 128
#define HID 256
#define DOUT 128
#define G4H (4*HID)        // 1024

// Scan tiling: 16 column-groups x 8 batch-groups = 128 CTAs
#define NCTA 128
#define JPC 16             // hidden units per CTA
#define NCOL 64            // gate columns per CTA
#define BPC 8              // batches per CTA
#define KTOT HID           // 256 (h only; x projected upfront)
#define KC 32              // K per warp (8 warps)
#define NTHREADS 256

// padded SMEM strides (floats) — all verified conflict-free
#define WSTR 260
#define HSTR 260
#define PSTR 68
#define XSTR 76

#define SM_W     0
#define SM_H     (SM_W + NCOL*WSTR)          // 16640
#define SM_PART  (SM_H + BPC*HSTR)           // +2080
#define SM_C     (SM_PART + 8*BPC*PSTR)      // +4352
#define SM_XP    (SM_C + JPC*BPC)            // +128
#define SM_FLOATS (SM_XP + BPC*XSTR)         // +608
#define SMEM_BYTES (SM_FLOATS*4)             // ~95 KB

// x_proj kernel smem
#define XP_XSTRIDE 133
#define XP_WSTRIDE 132
#define XPK_SX    0
#define XPK_SW    (128*XP_XSTRIDE)
#define XPK_FLOATS (XPK_SW + 128*XP_WSTRIDE)
#define XPK_BYTES (XPK_FLOATS*4)             // ~136 KB

// Global scratch (static; no allocations allowed)
__device__ __align__(16) float g_xp[(size_t)TSTEPS * 16 * 8 * 512]; // [t][cg][bg][bb*64+c] (512MB)
__device__ __align__(16) float g_h[2][8][16][JPC*BPC];              // [buf][bg][cg][lj*8+bb]
__device__ unsigned g_flags[8][16][32];                             // [bg][cg], 128B apart

__device__ __forceinline__ uint32_t smem_u32(const void* p) {
    return (uint32_t)__cvta_generic_to_shared(p);
}
__device__ __forceinline__ float fast_sig(float x) {
    return __fdividef(1.0f, 1.0f + __expf(-x));
}
__device__ __forceinline__ float fast_tanh(float x) {
    return __fdividef(2.0f, 1.0f + __expf(-2.0f * x)) - 1.0f;
}

// ---------------------------------------------------------------------------
__global__ void init_kernel() {
    int i = blockIdx.x * blockDim.x + threadIdx.x;
    if (i < 8 * 16 * 32) ((unsigned*)g_flags)[i] = 0u;
    if (i < 8 * 16 * JPC * BPC) ((float*)g_h[0])[i] = 0.0f;
}

// ---------------------------------------------------------------------------
// x_proj: g_xp[t][cg][bg][bb*64 + gate*16+lj] = x[b,t,:] . W_x[:, gcol] + bias
// CTA = (tblk of 16 timesteps, bg). 8 col-panels of 128.
// ---------------------------------------------------------------------------
__global__ void __launch_bounds__(NTHREADS, 1)
xproj_kernel(const float* __restrict__ x,
             const float* __restrict__ W_x,
             const float* __restrict__ bias) {
    extern __shared__ float smem[];
    float* sX = smem + XPK_SX;   // [r(128)][d] stride 133, r = tt*8+bb
    float* sW = smem + XPK_SW;   // [d][c(128)] stride 132

    const int tid  = threadIdx.x;
    const int tblk = blockIdx.x;
    const int bg   = blockIdx.y;

    // stage x tile: 128 rows x 128 d
    for (int idx = tid; idx < 128 * 32; idx += NTHREADS) {
        int r = idx >> 5, f4 = idx & 31;
        int tt = r >> 3, bb = r & 7;
        int b = bg * 8 + bb, t = tblk * 16 + tt;
        float4 v = __ldg(reinterpret_cast<const float4*>(
            x + ((size_t)b * TSTEPS + t) * DIN) + f4);
        float* dst = sX + r * XP_XSTRIDE + f4 * 4;
        dst[0] = v.x; dst[1] = v.y; dst[2] = v.z; dst[3] = v.w;
    }

    const int cq = tid & 7;       // 8 col-pair phases
    const int rg = tid >> 3;      // 32 row groups of 4

    for (int p = 0; p < 8; p++) {
        const int cp0 = p * 128;
        __syncthreads();
        // stage W panel [128 d][128 c]
        for (int idx = tid; idx < 128 * 32; idx += NTHREADS) {
            int d = idx >> 5, c4 = idx & 31;
            float4 v = __ldg(reinterpret_cast<const float4*>(
                W_x + (size_t)d * G4H + cp0) + c4);
            float* dst = sW + d * XP_WSTRIDE + c4 * 4;
            dst[0] = v.x; dst[1] = v.y; dst[2] = v.z; dst[3] = v.w;
        }
        __syncthreads();

        // acc[rr][qq] over c-pairs, init with bias
        unsigned long long acc[4][8];
        #pragma unroll
        for (int qq = 0; qq < 8; qq++) {
            float2 bv = __ldg(reinterpret_cast<const float2*>(
                bias + cp0 + 2 * (cq + 8 * qq)));
            unsigned long long bu;
            asm("mov.b64 %0, {%1, %2};" : "=l"(bu) : "f"(bv.x), "f"(bv.y));
            #pragma unroll
            for (int rr = 0; rr < 4; rr++) acc[rr][qq] = bu;
        }

        #pragma unroll 4
        for (int d = 0; d < 128; d++) {
            unsigned long long x2[4];
            #pragma unroll
            for (int rr = 0; rr < 4; rr++) {
                float xv = sX[(rg * 4 + rr) * XP_XSTRIDE + d];
                asm("mov.b64 %0, {%1, %1};" : "=l"(x2[rr]) : "f"(xv));
            }
            const uint32_t wrow = smem_u32(sW + d * XP_WSTRIDE + 2 * cq);
            #pragma unroll
            for (int qq = 0; qq < 8; qq++) {
                unsigned long long w2;
                asm volatile("ld.shared.u64 %0, [%1];"
                             : "=l"(w2) : "r"(wrow + qq * 64));
                #pragma unroll
                for (int rr = 0; rr < 4; rr++)
                    asm volatile("fma.rn.f32x2 %0, %1, %2, %0;"
                                 : "+l"(acc[rr][qq]) : "l"(x2[rr]), "l"(w2));
            }
        }

        // store: scatter into scan layout
        #pragma unroll
        for (int rr = 0; rr < 4; rr++) {
            int r = rg * 4 + rr;
            int tt = r >> 3, bb = r & 7;
            int t = tblk * 16 + tt;
            #pragma unroll
            for (int qq = 0; qq < 8; qq++) {
                int cglob = cp0 + 2 * (cq + 8 * qq);
                int gate = cglob >> 8, rem = cglob & 255;
                int cg = rem >> 4, lj = rem & 15;
                float lo, hi;
                asm("mov.b64 {%0,%1}, %2;" : "=f"(lo), "=f"(hi) : "l"(acc[rr][qq]));
                float2* dst = reinterpret_cast<float2*>(
                    g_xp + ((size_t)((t * 16 + cg) * 8 + bg)) * 512
                         + bb * 64 + gate * 16 + lj);
                *dst = make_float2(lo, hi);
            }
        }
    }
}

// ---------------------------------------------------------------------------
// persistent LSTM scan: CTA (cg, bg); per-producer flags, per-warp consume
// ---------------------------------------------------------------------------
__global__ void __launch_bounds__(NTHREADS, 1)
lstm_scan_kernel(const float* __restrict__ W_h) {
    extern __shared__ float smem[];
    float* sW    = smem + SM_W;     // [c][k], c = gate*16+lj
    float* sH    = smem + SM_H;     // [b][k]
    float* sPart = smem + SM_PART;  // [kc][b][c]
    float* sC    = smem + SM_C;     // [lj*8+bb]
    float* sXP   = smem + SM_XP;    // [bb][c] stride XSTR

    const int tid = threadIdx.x;
    const int cg  = blockIdx.x & 15;
    const int bg  = blockIdx.x >> 4;
    const int j0  = cg * JPC;

    // stage W_h slice: sW[c][k], 64 cols x 256 k
    for (int idx = tid; idx < NCOL * KTOT; idx += NTHREADS) {
        int k = idx >> 6, c = idx & 63;
        int gate = c >> 4, lj = c & 15;
        sW[c * WSTR + k] = W_h[(size_t)k * G4H + gate * HID + j0 + lj];
    }
    if (tid < JPC * BPC) sC[tid] = 0.0f;
    __syncthreads();

    // compute decode
    const int lane = tid & 31;
    const int cq   = lane & 7;
    const int bp   = lane >> 3;          // 0..3
    const int kc   = tid >> 5;           // warp = k-chunk
    const int k0   = kc * KC;

    const uint32_t haddr0 = smem_u32(sH + (2 * bp) * HSTR + k0);
    const uint32_t haddr1 = smem_u32(sH + (2 * bp + 1) * HSTR + k0);
    const uint32_t waddr  = smem_u32(sW + cq * WSTR + k0);

    unsigned* myflag = &g_flags[bg][cg][0];

    for (int s = 0; s < TSTEPS; s++) {
        const int rbuf = s & 1;

        // ---- prefetch x_proj slice (ready since xproj_kernel; 2 floats/thread)
        float2 xp = __ldg(reinterpret_cast<const float2*>(
            g_xp + ((size_t)((s * 16 + cg) * 8 + bg)) * 512) + tid);

        // ---- per-warp wait on my two producers
        if (s > 0) {
            if (lane < 2) {
                unsigned* f = &g_flags[bg][2 * kc + lane][0];
                unsigned v;
                do {
                    asm volatile("ld.acquire.gpu.global.u32 %0, [%1];"
                                 : "=r"(v) : "l"(f) : "memory");
                } while (v < (unsigned)s);
            }
            __syncwarp();
        }

        // ---- pull my 2 h blocks (1KB) and transpose into my sH k-rows
        {
            const float4* pA = reinterpret_cast<const float4*>(g_h[rbuf][bg][2 * kc]);
            const float4* pB = reinterpret_cast<const float4*>(g_h[rbuf][bg][2 * kc + 1]);
            float4 a = __ldcg(pA + lane);
            float4 bv = __ldcg(pB + lane);
            int e = 4 * lane;
            // block A: k = k0 + lj ; block B: k = k0 + 16 + lj
            sH[((e + 0) & 7) * HSTR + k0 + ((e + 0) >> 3)]      = a.x;
            sH[((e + 1) & 7) * HSTR + k0 + ((e + 1) >> 3)]      = a.y;
            sH[((e + 2) & 7) * HSTR + k0 + ((e + 2) >> 3)]      = a.z;
            sH[((e + 3) & 7) * HSTR + k0 + ((e + 3) >> 3)]      = a.w;
            sH[((e + 0) & 7) * HSTR + k0 + 16 + ((e + 0) >> 3)] = bv.x;
            sH[((e + 1) & 7) * HSTR + k0 + 16 + ((e + 1) >> 3)] = bv.y;
            sH[((e + 2) & 7) * HSTR + k0 + 16 + ((e + 2) >> 3)] = bv.z;
            sH[((e + 3) & 7) * HSTR + k0 + 16 + ((e + 3) >> 3)] = bv.w;
        }
        // ---- store xp into sXP (read by epilogue after syncthreads)
        {
            int i0 = tid * 2;
            float* dst = sXP + (i0 >> 6) * XSTR + (i0 & 63);
            dst[0] = xp.x; dst[1] = xp.y;
        }
        __syncwarp();

        // ---- partial GEMM: 8 cols x 2 batches x 32 k, f32x2 along K
        unsigned long long a0[8], a1[8];
        #pragma unroll
        for (int q = 0; q < 8; q++) { a0[q] = 0ull; a1[q] = 0ull; }

        #pragma unroll
        for (int kk = 0; kk < KC; kk += 4) {
            unsigned long long h01a, h23a, h01b, h23b;
            asm volatile("ld.shared.v2.u64 {%0,%1}, [%2];"
                         : "=l"(h01a), "=l"(h23a) : "r"(haddr0 + kk * 4));
            asm volatile("ld.shared.v2.u64 {%0,%1}, [%2];"
                         : "=l"(h01b), "=l"(h23b) : "r"(haddr1 + kk * 4));
            #pragma unroll
            for (int q = 0; q < 8; q++) {
                unsigned long long w01, w23;
                asm volatile("ld.shared.v2.u64 {%0,%1}, [%2];"
                             : "=l"(w01), "=l"(w23)
                             : "r"(waddr + (q * (8 * WSTR) + kk) * 4));
                asm volatile("fma.rn.f32x2 %0, %1, %2, %0;"
                             : "+l"(a0[q]) : "l"(h01a), "l"(w01));
                asm volatile("fma.rn.f32x2 %0, %1, %2, %0;"
                             : "+l"(a0[q]) : "l"(h23a), "l"(w23));
                asm volatile("fma.rn.f32x2 %0, %1, %2, %0;"
                             : "+l"(a1[q]) : "l"(h01b), "l"(w01));
                asm volatile("fma.rn.f32x2 %0, %1, %2, %0;"
                             : "+l"(a1[q]) : "l"(h23b), "l"(w23));
            }
        }

        // ---- horizontal add + partials (bank = 8bp+cq +4, conflict-free)
        #pragma unroll
        for (int q = 0; q < 8; q++) {
            int c = cq + 8 * q;
            float lo, hi;
            asm("mov.b64 {%0,%1}, %2;" : "=f"(lo), "=f"(hi) : "l"(a0[q]));
            sPart[(kc * BPC + 2 * bp) * PSTR + c] = lo + hi;
            asm("mov.b64 {%0,%1}, %2;" : "=f"(lo), "=f"(hi) : "l"(a1[q]));
            sPart[(kc * BPC + 2 * bp + 1) * PSTR + c] = lo + hi;
        }
        __syncthreads();

        // ---- epilogue: 128 threads = (lj, bb)
        if (tid < JPC * BPC) {
            int lj = tid >> 3;
            int bb = tid & 7;
            float g4[4];
            #pragma unroll
            for (int gate = 0; gate < 4; gate++) {
                int c = gate * JPC + lj;
                float v = sXP[bb * XSTR + c];
                #pragma unroll
                for (int q = 0; q < 8; q++)
                    v += sPart[(q * BPC + bb) * PSTR + c];
                g4[gate] = v;
            }
            float ig = fast_sig(g4[0]);
            float fg = fast_sig(g4[1]);
            float gg = fast_tanh(g4[2]);
            float og = fast_sig(g4[3]);
            float cnew = fg * sC[tid] + ig * gg;
            sC[tid] = cnew;
            float hnew = og * fast_tanh(cnew);
            __stcg(&g_h[rbuf ^ 1][bg][cg][tid], hnew);  // 512B coalesced
        }
        __syncthreads();

        // ---- publish (release orders the h stores via bar.sync + release)
        if (tid == 0) {
            asm volatile("st.release.gpu.global.u32 [%0], %1;"
                         :: "l"(myflag), "r"((unsigned)(s + 1)) : "memory");
        }
    }
}

// ---------------------------------------------------------------------------
// final FC: out[b][d] = sum_k h_final[k][b] * fc_w[k][d] + fc_b[d]
// final h is in g_h[0][bg][cg][lj*8+bb]
// ---------------------------------------------------------------------------
__global__ void fc_kernel(const float* __restrict__ fc_w,
                          const float* __restrict__ fc_b,
                          float* __restrict__ out) {
    int b = blockIdx.x;
    int d = threadIdx.x;
    int bg = b >> 3, bb = b & 7;
    float acc = fc_b[d];
    #pragma unroll 8
    for (int k = 0; k < HID; k++)
        acc += g_h[0][bg][k >> 4][(k & 15) * 8 + bb] * fc_w[k * DOUT + d];
    out[b * DOUT + d] = acc;
}

// ---------------------------------------------------------------------------
extern "C" void kernel_launch(void* const* d_in, const int* in_sizes, int n_in,
                              void* d_out, int out_size) {
    const float* x    = (const float*)d_in[0];
    const float* W_x  = (const float*)d_in[1];
    const float* W_h  = (const float*)d_in[2];
    const float* bvec = (const float*)d_in[3];
    const float* fc_w = (const float*)d_in[4];
    const float* fc_b = (const float*)d_in[5];
    float* out = (float*)d_out;

    cudaFuncSetAttribute(lstm_scan_kernel,
                         cudaFuncAttributeMaxDynamicSharedMemorySize, SMEM_BYTES);
    cudaFuncSetAttribute(xproj_kernel,
                         cudaFuncAttributeMaxDynamicSharedMemorySize, XPK_BYTES);

    init_kernel<<<(8 * 16 * 128 + 255) / 256, 256>>>();
    xproj_kernel<<<dim3(TSTEPS / 16, 8), NTHREADS, XPK_BYTES>>>(x, W_x, bvec);
    lstm_scan_kernel<<<NCTA, NTHREADS, SMEM_BYTES>>>(W_h);
    fc_kernel<<<BATCH, DOUT>>>(fc_w, fc_b, out);
}